// round 14
// baseline (speedup 1.0000x reference)
#include <cuda_runtime.h>

#define B_  128
#define A_  2048
#define C_  128
#define H_  512
#define S_  3
#define NR_ 2
#define PR_ 134                 // C + 3 + S
#define PW_ 390                 // 3C + 3 + S
#define NP_ (NR_*PR_ + PW_)     // 658 total params per batch row

// ---------------- scratch (device globals; no allocation allowed) ----------
__device__ float g_params[B_ * NP_];       // raw projections, [b][p]
__device__ float g_q[3 * B_ * C_];         // sigmoid(q) per head, [head][b][c]
__device__ float g_scal[3 * B_ * 8];       // qn, beta, gate, sw0..2, gamma
__device__ float g_sim[3 * B_ * A_];       // cosine sims
__device__ float g_w[3 * B_ * A_];         // final attention weights

__device__ __forceinline__ float sigmoidf_(float x) { return 1.f / (1.f + expf(-x)); }
__device__ __forceinline__ float softplusf_(float x) {
    return fmaxf(x, 0.f) + log1pf(expf(-fabsf(x)));
}

// ---------------- block reductions (256 threads) ---------------------------
__device__ __forceinline__ float blockSum256(float v, float* buf) {
    int t = threadIdx.x;
    #pragma unroll
    for (int o = 16; o; o >>= 1) v += __shfl_xor_sync(0xffffffffu, v, o);
    if ((t & 31) == 0) buf[t >> 5] = v;
    __syncthreads();
    if (t == 0) { float s = 0.f; for (int i = 0; i < 8; i++) s += buf[i]; buf[8] = s; }
    __syncthreads();
    float r = buf[8];
    __syncthreads();
    return r;
}
__device__ __forceinline__ float blockMax256(float v, float* buf) {
    int t = threadIdx.x;
    #pragma unroll
    for (int o = 16; o; o >>= 1) v = fmaxf(v, __shfl_xor_sync(0xffffffffu, v, o));
    if ((t & 31) == 0) buf[t >> 5] = v;
    __syncthreads();
    if (t == 0) { float s = buf[0]; for (int i = 1; i < 8; i++) s = fmaxf(s, buf[i]); buf[8] = s; }
    __syncthreads();
    float r = buf[8];
    __syncthreads();
    return r;
}

// ---------------- k_proj: [B,H] @ [H, NP]^T  (smem-tiled GEMM) --------------
__global__ void k_proj(const float* __restrict__ h,
                       const float* __restrict__ Wr, const float* __restrict__ br,
                       const float* __restrict__ Ww, const float* __restrict__ bw)
{
    __shared__ float hs[128 * 33];
    __shared__ float ws[8 * 33];
    int t = threadIdx.x;
    int pblk = blockIdx.x * 8;
    int p_l = t & 7, bs = t >> 3;
    float acc0 = 0.f, acc1 = 0.f, acc2 = 0.f, acc3 = 0.f;

    for (int k0 = 0; k0 < H_; k0 += 32) {
        {
            int pl = t >> 5, kk = t & 31;
            int p = pblk + pl;
            float v = 0.f;
            if (p < NP_) {
                const float* row = (p < NR_*PR_) ? (Wr + (size_t)p * H_)
                                                 : (Ww + (size_t)(p - NR_*PR_) * H_);
                v = row[k0 + kk];
            }
            ws[pl * 33 + kk] = v;
        }
        for (int x = t; x < 4096; x += 256) {
            int bb = x >> 5, kk = x & 31;
            hs[bb * 33 + kk] = h[bb * H_ + k0 + kk];
        }
        __syncthreads();
        #pragma unroll
        for (int kk = 0; kk < 32; kk++) {
            float w = ws[p_l * 33 + kk];
            acc0 = fmaf(hs[(bs      ) * 33 + kk], w, acc0);
            acc1 = fmaf(hs[(bs +  32) * 33 + kk], w, acc1);
            acc2 = fmaf(hs[(bs +  64) * 33 + kk], w, acc2);
            acc3 = fmaf(hs[(bs +  96) * 33 + kk], w, acc3);
        }
        __syncthreads();
    }
    int p = pblk + p_l;
    if (p < NP_) {
        float bias = (p < NR_*PR_) ? br[p] : bw[p - NR_*PR_];
        g_params[(bs      ) * NP_ + p] = acc0 + bias;
        g_params[(bs +  32) * NP_ + p] = acc1 + bias;
        g_params[(bs +  64) * NP_ + p] = acc2 + bias;
        g_params[(bs +  96) * NP_ + p] = acc3 + bias;
    }
}

// ---------------- k_prep: activations + scalars + zero read-vector out ------
// grid B, 128 threads (thread = channel c)
__global__ void k_prep(float* __restrict__ out)
{
    __shared__ float red[8];
    int b = blockIdx.x, t = threadIdx.x;
    // zero the read_vectors region of out: 32768 floats total
    out[b * 256 + t]       = 0.f;
    out[b * 256 + 128 + t] = 0.f;
    for (int head = 0; head < 3; head++) {
        int base = (head < 2) ? head * PR_ : NR_ * PR_;
        float raw = g_params[b * NP_ + base + t];
        float qv = sigmoidf_(raw);
        g_q[(head * B_ + b) * C_ + t] = qv;
        float ss = qv * qv;
        #pragma unroll
        for (int o = 16; o; o >>= 1) ss += __shfl_xor_sync(0xffffffffu, ss, o);
        if ((t & 31) == 0) red[t >> 5] = ss;
        __syncthreads();
        if (t == 0) {
            float s = red[0] + red[1] + red[2] + red[3];
            float* sc = g_scal + (head * B_ + b) * 8;
            sc[0] = fmaxf(sqrtf(s), 1e-8f);
            const float* pp = g_params + b * NP_ + base + C_;
            sc[1] = softplusf_(pp[0]) + 1.f;
            sc[2] = sigmoidf_(pp[1]);
            float s0 = pp[2], s1 = pp[3], s2 = pp[4];
            float mx = fmaxf(s0, fmaxf(s1, s2));
            float e0 = expf(s0 - mx), e1 = expf(s1 - mx), e2 = expf(s2 - mx);
            float iz = 1.f / (e0 + e1 + e2);
            sc[3] = e0 * iz; sc[4] = e1 * iz; sc[5] = e2 * iz;
            sc[6] = softplusf_(pp[5]) + 1.f;
        }
        __syncthreads();
    }
}

// ---------------- k_sim: cosine similarity, smem-staged, conflict-free ------
// grid B*64 blocks, 256 threads. Block = 32 a-rows. Stride-136 smem pad makes
// phase-2 LDS bank-bijective (bank = 8*(t&3) + sub + 8k mod 32).
#define TSTRIDE 136
__global__ void k_sim(const float* __restrict__ mem)
{
    __shared__ float tile[32 * TSTRIDE];
    __shared__ float qsm[3 * 128];
    __shared__ float iqn[3];
    int bx = blockIdx.x;
    int b  = bx >> 6;
    int a0 = (bx & 63) * 32;
    int t  = threadIdx.x;

    // stage q (L1/L2-resident, tiny)
    if (t < 128) {
        qsm[t]       = g_q[(0 * B_ + b) * C_ + t];
        qsm[128 + t] = g_q[(1 * B_ + b) * C_ + t];
        qsm[256 + t] = g_q[(2 * B_ + b) * C_ + t];
    } else if (t < 131) {
        iqn[t - 128] = 1.f / g_scal[((t - 128) * B_ + b) * 8];
    }

    // phase 1: coalesced float4 load of 32 rows into padded smem
    const float4* m4 = (const float4*)mem + ((size_t)b * A_ + a0) * 32;
    float4* tile4 = (float4*)tile;
    #pragma unroll
    for (int pass = 0; pass < 4; pass++) {
        int i = t + pass * 256;            // i in [0,1024)
        int r = i >> 5, c4 = i & 31;
        tile4[r * (TSTRIDE / 4) + c4] = __ldcg(m4 + i);   // keep in L2 for k_update
    }
    __syncthreads();

    // phase 2: 8 threads per row; thread covers c = sub + 8k, k=0..15
    int r4  = t & 3;                        // row within warp group
    int sub = (t >> 2) & 7;
    int w   = t >> 5;
    int row = w * 4 + r4;                   // 0..31
    const float* trow = tile + row * TSTRIDE;

    float nn = 0.f, d0 = 0.f, d1 = 0.f, d2 = 0.f;
    #pragma unroll
    for (int k = 0; k < 16; k++) {
        int c = sub + 8 * k;
        float m = trow[c];
        nn = fmaf(m, m, nn);
        d0 = fmaf(m, qsm[c],       d0);
        d1 = fmaf(m, qsm[128 + c], d1);
        d2 = fmaf(m, qsm[256 + c], d2);
    }
    // reduce over sub (lanes differing in bits 2..4)
    #pragma unroll
    for (int o = 4; o <= 16; o <<= 1) {
        nn += __shfl_xor_sync(0xffffffffu, nn, o);
        d0 += __shfl_xor_sync(0xffffffffu, d0, o);
        d1 += __shfl_xor_sync(0xffffffffu, d1, o);
        d2 += __shfl_xor_sync(0xffffffffu, d2, o);
    }
    if (sub == 0) {
        int aa = a0 + row;
        float imn = 1.f / fmaxf(sqrtf(nn), 1e-8f);
        g_sim[((size_t)(0 * B_ + b)) * A_ + aa] = d0 * iqn[0] * imn;
        g_sim[((size_t)(1 * B_ + b)) * A_ + aa] = d1 * iqn[1] * imn;
        g_sim[((size_t)(2 * B_ + b)) * A_ + aa] = d2 * iqn[2] * imn;
    }
}

// ---------------- k_addr: softmax + gate + shift + sharpen ------------------
__global__ void k_addr(const float* __restrict__ prev_ra,
                       const float* __restrict__ prev_wa)
{
    __shared__ float wg[A_];
    __shared__ float buf[16];
    int b = blockIdx.x, head = blockIdx.y, t = threadIdx.x;
    const float* sc = g_scal + (head * B_ + b) * 8;
    float beta = sc[1], gate = sc[2];
    float sw0 = sc[3], sw1 = sc[4], sw2 = sc[5], gamma = sc[6];

    const float* simrow = g_sim + ((size_t)(head * B_ + b)) * A_;
    float v[8];
    float mx = -1e30f;
    #pragma unroll
    for (int i = 0; i < 8; i++) { v[i] = simrow[t + i * 256]; mx = fmaxf(mx, v[i]); }
    mx = blockMax256(mx, buf);

    float s = 0.f;
    #pragma unroll
    for (int i = 0; i < 8; i++) { v[i] = __expf(beta * (v[i] - mx)); s += v[i]; }
    float Z = blockSum256(s, buf);

    const float* prev = (head < 2) ? (prev_ra + ((size_t)(head * B_ + b)) * A_)
                                   : (prev_wa + (size_t)b * A_);
    float gz = gate / Z, og = 1.f - gate;
    #pragma unroll
    for (int i = 0; i < 8; i++) {
        int a = t + i * 256;
        wg[a] = gz * v[i] + og * prev[a];
    }
    __syncthreads();

    float p[8];
    float ps = 0.f;
    #pragma unroll
    for (int i = 0; i < 8; i++) {
        int a = t + i * 256;
        float wsa = wg[(a + 1) & (A_ - 1)] * sw0 + wg[a] * sw1 + wg[(a - 1) & (A_ - 1)] * sw2;
        p[i] = __powf(wsa, gamma);
        ps += p[i];
    }
    float SP = blockSum256(ps, buf);
    float inv = 1.f / (SP + 1e-12f);
    float* wrow = g_w + ((size_t)(head * B_ + b)) * A_;
    #pragma unroll
    for (int i = 0; i < 8; i++) wrow[t + i * 256] = p[i] * inv;
}

// ---------------- k_update: float4, reversed order for L2 reuse -------------
// grid B*32, 256 threads (8 warps). Block = 64 a-rows; warp = 8 rows;
// lane = 4 channels (one float4 = full 512B row per warp per step).
__global__ void k_update(const float* __restrict__ mem, float* __restrict__ out)
{
    __shared__ float wsm[3 * 64];
    __shared__ float rvs[2 * 8 * 128];     // [head][warp][c]
    int idx = gridDim.x - 1 - blockIdx.x;  // reversed: hit k_sim's L2 tail first
    int b   = idx >> 5;
    int a0  = (idx & 31) * 64;
    int t   = threadIdx.x;
    int w   = t >> 5, lane = t & 31;

    if (t < 192) {
        int head = t >> 6, aa = t & 63;
        wsm[t] = g_w[((size_t)(head * B_ + b)) * A_ + a0 + aa];
    }
    // erase / add for this lane's 4 channels
    float4 ev, av;
    {
        const float* pe = g_params + b * NP_ + NR_*PR_ +     C_ + 6 + lane * 4;
        const float* pa = g_params + b * NP_ + NR_*PR_ + 2 * C_ + 6 + lane * 4;
        ev.x = sigmoidf_(pe[0]); ev.y = sigmoidf_(pe[1]);
        ev.z = sigmoidf_(pe[2]); ev.w = sigmoidf_(pe[3]);
        av.x = sigmoidf_(pa[0]); av.y = sigmoidf_(pa[1]);
        av.z = sigmoidf_(pa[2]); av.w = sigmoidf_(pa[3]);
    }
    __syncthreads();

    const float4* mrow = (const float4*)mem + ((size_t)b * A_ + a0 + w * 8) * 32 + lane;
    float4* orow = (float4*)(out + (size_t)NR_ * B_ * C_)
                   + ((size_t)b * A_ + a0 + w * 8) * 32 + lane;

    float4 m[8];
    #pragma unroll
    for (int i = 0; i < 8; i++) m[i] = __ldcg(mrow + (size_t)i * 32);

    float4 rv0 = {0,0,0,0}, rv1 = {0,0,0,0};
    #pragma unroll
    for (int i = 0; i < 8; i++) {
        int aa = w * 8 + i;
        float w0 = wsm[aa], w1 = wsm[64 + aa], w2 = wsm[128 + aa];
        rv0.x = fmaf(w0, m[i].x, rv0.x); rv0.y = fmaf(w0, m[i].y, rv0.y);
        rv0.z = fmaf(w0, m[i].z, rv0.z); rv0.w = fmaf(w0, m[i].w, rv0.w);
        rv1.x = fmaf(w1, m[i].x, rv1.x); rv1.y = fmaf(w1, m[i].y, rv1.y);
        rv1.z = fmaf(w1, m[i].z, rv1.z); rv1.w = fmaf(w1, m[i].w, rv1.w);
        float4 o;
        o.x = fmaf(w2, av.x, m[i].x * (1.f - w2 * ev.x));
        o.y = fmaf(w2, av.y, m[i].y * (1.f - w2 * ev.y));
        o.z = fmaf(w2, av.z, m[i].z * (1.f - w2 * ev.z));
        o.w = fmaf(w2, av.w, m[i].w * (1.f - w2 * ev.w));
        __stcs(orow + (size_t)i * 32, o);
    }

    // cross-warp reduce of read-vector partials, then one atomic per (head,c)
    int c = lane * 4;
    rvs[(0 * 8 + w) * 128 + c]     = rv0.x;
    rvs[(0 * 8 + w) * 128 + c + 1] = rv0.y;
    rvs[(0 * 8 + w) * 128 + c + 2] = rv0.z;
    rvs[(0 * 8 + w) * 128 + c + 3] = rv0.w;
    rvs[(1 * 8 + w) * 128 + c]     = rv1.x;
    rvs[(1 * 8 + w) * 128 + c + 1] = rv1.y;
    rvs[(1 * 8 + w) * 128 + c + 2] = rv1.z;
    rvs[(1 * 8 + w) * 128 + c + 3] = rv1.w;
    __syncthreads();

    int head = t >> 7, cc = t & 127;
    float s = 0.f;
    #pragma unroll
    for (int ww = 0; ww < 8; ww++) s += rvs[(head * 8 + ww) * 128 + cc];
    atomicAdd(out + ((size_t)(head * B_ + b)) * C_ + cc, s);
}

// ---------------- launch -----------------------------------------------------
extern "C" void kernel_launch(void* const* d_in, const int* in_sizes, int n_in,
                              void* d_out, int out_size)
{
    const float* h   = (const float*)d_in[0];   // [B,H]
    const float* mem = (const float*)d_in[1];   // [B,A,C]
    const float* pra = (const float*)d_in[2];   // [NR,B,A]
    const float* pwa = (const float*)d_in[3];   // [B,A]
    const float* Wr  = (const float*)d_in[4];   // [NR,PR,H]
    const float* br  = (const float*)d_in[5];   // [NR,PR]
    const float* Ww  = (const float*)d_in[6];   // [PW,H]
    const float* bw  = (const float*)d_in[7];   // [PW]
    float* out = (float*)d_out;                 // [NR*B*C + B*A*C]

    k_proj<<<(NP_ + 7) / 8, 256>>>(h, Wr, br, Ww, bw);
    k_prep<<<B_, 128>>>(out);
    k_sim<<<B_ * 64, 256>>>(mem);
    dim3 ga(B_, 3);
    k_addr<<<ga, 256>>>(pra, pwa);
    k_update<<<B_ * 32, 256>>>(mem, out);
}

// round 16
// speedup vs baseline: 1.8046x; 1.8046x over previous
#include <cuda_runtime.h>

#define B_  128
#define A_  2048
#define C_  128
#define H_  512
#define S_  3
#define NR_ 2
#define PR_ 134                 // C + 3 + S
#define PW_ 390                 // 3C + 3 + S
#define NP_ (NR_*PR_ + PW_)     // 658 total params per batch row

// ---------------- scratch (device globals; no allocation allowed) ----------
__device__ float g_params[B_ * NP_];       // raw projections, [b][p]
__device__ float g_q[3 * B_ * C_];         // sigmoid(q) per head, [head][b][c]
__device__ float g_scal[3 * B_ * 8];       // qn, beta, gate, sw0..2, gamma
__device__ float g_sim[3 * B_ * A_];       // cosine sims
__device__ float g_w[3 * B_ * A_];         // final attention weights

__device__ __forceinline__ float sigmoidf_(float x) { return 1.f / (1.f + expf(-x)); }
__device__ __forceinline__ float softplusf_(float x) {
    return fmaxf(x, 0.f) + log1pf(expf(-fabsf(x)));
}

// ---------------- block reductions (256 threads) ---------------------------
__device__ __forceinline__ float blockSum256(float v, float* buf) {
    int t = threadIdx.x;
    #pragma unroll
    for (int o = 16; o; o >>= 1) v += __shfl_xor_sync(0xffffffffu, v, o);
    if ((t & 31) == 0) buf[t >> 5] = v;
    __syncthreads();
    if (t == 0) { float s = 0.f; for (int i = 0; i < 8; i++) s += buf[i]; buf[8] = s; }
    __syncthreads();
    float r = buf[8];
    __syncthreads();
    return r;
}
__device__ __forceinline__ float blockMax256(float v, float* buf) {
    int t = threadIdx.x;
    #pragma unroll
    for (int o = 16; o; o >>= 1) v = fmaxf(v, __shfl_xor_sync(0xffffffffu, v, o));
    if ((t & 31) == 0) buf[t >> 5] = v;
    __syncthreads();
    if (t == 0) { float s = buf[0]; for (int i = 1; i < 8; i++) s = fmaxf(s, buf[i]); buf[8] = s; }
    __syncthreads();
    float r = buf[8];
    __syncthreads();
    return r;
}

// ---------------- k_proj: [B,H] @ [H, NP]^T  (smem-tiled GEMM) --------------
// grid (83, 4): x = 8-param block, y = 32-b group. 256 threads, 1 output each.
__global__ void k_proj(const float* __restrict__ h,
                       const float* __restrict__ Wr, const float* __restrict__ br,
                       const float* __restrict__ Ww, const float* __restrict__ bw)
{
    __shared__ float hs[32 * 33];
    __shared__ float ws[8 * 33];
    int t = threadIdx.x;
    int pblk = blockIdx.x * 8;
    int bg   = blockIdx.y * 32;
    int p_l = t & 7, bs = t >> 3;    // bs in 0..31
    float acc = 0.f;

    for (int k0 = 0; k0 < H_; k0 += 32) {
        {   // weight tile: 8 rows x 32
            int pl = t >> 5, kk = t & 31;
            int p = pblk + pl;
            float v = 0.f;
            if (p < NP_) {
                const float* row = (p < NR_*PR_) ? (Wr + (size_t)p * H_)
                                                 : (Ww + (size_t)(p - NR_*PR_) * H_);
                v = row[k0 + kk];
            }
            ws[pl * 33 + kk] = v;
        }
        // h tile: 32 b x 32 k
        {
            int x = t;
            #pragma unroll
            for (int pass = 0; pass < 4; pass++, x += 256) {
                int bb = x >> 5, kk = x & 31;
                hs[bb * 33 + kk] = h[(bg + bb) * H_ + k0 + kk];
            }
        }
        __syncthreads();
        #pragma unroll
        for (int kk = 0; kk < 32; kk++)
            acc = fmaf(hs[bs * 33 + kk], ws[p_l * 33 + kk], acc);
        __syncthreads();
    }
    int p = pblk + p_l;
    if (p < NP_) {
        float bias = (p < NR_*PR_) ? br[p] : bw[p - NR_*PR_];
        g_params[(bg + bs) * NP_ + p] = acc + bias;
    }
}

// ---------------- k_prep: activations + scalars + zero read-vector out ------
// grid B, 128 threads (thread = channel c)
__global__ void k_prep(float* __restrict__ out)
{
    __shared__ float red[8];
    int b = blockIdx.x, t = threadIdx.x;
    // zero the read_vectors region of out: 32768 floats total
    out[b * 256 + t]       = 0.f;
    out[b * 256 + 128 + t] = 0.f;
    for (int head = 0; head < 3; head++) {
        int base = (head < 2) ? head * PR_ : NR_ * PR_;
        float raw = g_params[b * NP_ + base + t];
        float qv = sigmoidf_(raw);
        g_q[(head * B_ + b) * C_ + t] = qv;
        float ss = qv * qv;
        #pragma unroll
        for (int o = 16; o; o >>= 1) ss += __shfl_xor_sync(0xffffffffu, ss, o);
        if ((t & 31) == 0) red[t >> 5] = ss;
        __syncthreads();
        if (t == 0) {
            float s = red[0] + red[1] + red[2] + red[3];
            float* sc = g_scal + (head * B_ + b) * 8;
            sc[0] = fmaxf(sqrtf(s), 1e-8f);
            const float* pp = g_params + b * NP_ + base + C_;
            sc[1] = softplusf_(pp[0]) + 1.f;
            sc[2] = sigmoidf_(pp[1]);
            float s0 = pp[2], s1 = pp[3], s2 = pp[4];
            float mx = fmaxf(s0, fmaxf(s1, s2));
            float e0 = expf(s0 - mx), e1 = expf(s1 - mx), e2 = expf(s2 - mx);
            float iz = 1.f / (e0 + e1 + e2);
            sc[3] = e0 * iz; sc[4] = e1 * iz; sc[5] = e2 * iz;
            sc[6] = softplusf_(pp[5]) + 1.f;
        }
        __syncthreads();
    }
}

// ---------------- k_sim: cosine similarity (R13 form, measured-good) --------
// grid B*64, 256 threads (8 warps). Warp handles 4 rows; lane = float4 chunk.
__global__ void k_sim(const float* __restrict__ mem)
{
    int bx   = blockIdx.x;
    int b    = bx >> 6;
    int a0   = (bx & 63) * 32;
    int warp = threadIdx.x >> 5, lane = threadIdx.x & 31;

    const float4* q0p = (const float4*)(g_q + (0 * B_ + b) * C_);
    const float4* q1p = (const float4*)(g_q + (1 * B_ + b) * C_);
    const float4* q2p = (const float4*)(g_q + (2 * B_ + b) * C_);
    float4 q0 = q0p[lane], q1 = q1p[lane], q2 = q2p[lane];
    float iqn0 = 1.f / g_scal[(0 * B_ + b) * 8];
    float iqn1 = 1.f / g_scal[(1 * B_ + b) * 8];
    float iqn2 = 1.f / g_scal[(2 * B_ + b) * 8];

    int a = a0 + warp * 4;
    const float4* m4 = (const float4*)mem + ((size_t)b * A_ + a) * 32;

    float nn[4], d0[4], d1[4], d2[4];
    #pragma unroll
    for (int j = 0; j < 4; j++) {
        float4 m = __ldcs(m4 + (size_t)j * 32 + lane);
        nn[j] = m.x*m.x + m.y*m.y + m.z*m.z + m.w*m.w;
        d0[j] = m.x*q0.x + m.y*q0.y + m.z*q0.z + m.w*q0.w;
        d1[j] = m.x*q1.x + m.y*q1.y + m.z*q1.z + m.w*q1.w;
        d2[j] = m.x*q2.x + m.y*q2.y + m.z*q2.z + m.w*q2.w;
    }
    #pragma unroll
    for (int j = 0; j < 4; j++) {
        #pragma unroll
        for (int o = 16; o; o >>= 1) {
            nn[j] += __shfl_xor_sync(0xffffffffu, nn[j], o);
            d0[j] += __shfl_xor_sync(0xffffffffu, d0[j], o);
            d1[j] += __shfl_xor_sync(0xffffffffu, d1[j], o);
            d2[j] += __shfl_xor_sync(0xffffffffu, d2[j], o);
        }
    }
    if (lane < 4) {
        int j  = lane;
        int aa = a + j;
        float sn = (j == 0) ? nn[0] : (j == 1) ? nn[1] : (j == 2) ? nn[2] : nn[3];
        float s0 = (j == 0) ? d0[0] : (j == 1) ? d0[1] : (j == 2) ? d0[2] : d0[3];
        float s1 = (j == 0) ? d1[0] : (j == 1) ? d1[1] : (j == 2) ? d1[2] : d1[3];
        float s2 = (j == 0) ? d2[0] : (j == 1) ? d2[1] : (j == 2) ? d2[2] : d2[3];
        float imn = 1.f / fmaxf(sqrtf(sn), 1e-8f);
        g_sim[((size_t)(0 * B_ + b)) * A_ + aa] = s0 * iqn0 * imn;
        g_sim[((size_t)(1 * B_ + b)) * A_ + aa] = s1 * iqn1 * imn;
        g_sim[((size_t)(2 * B_ + b)) * A_ + aa] = s2 * iqn2 * imn;
    }
}

// ---------------- k_addr: softmax + gate + shift + sharpen ------------------
__global__ void k_addr(const float* __restrict__ prev_ra,
                       const float* __restrict__ prev_wa)
{
    __shared__ float wg[A_];
    __shared__ float buf[16];
    int b = blockIdx.x, head = blockIdx.y, t = threadIdx.x;
    const float* sc = g_scal + (head * B_ + b) * 8;
    float beta = sc[1], gate = sc[2];
    float sw0 = sc[3], sw1 = sc[4], sw2 = sc[5], gamma = sc[6];

    const float* simrow = g_sim + ((size_t)(head * B_ + b)) * A_;
    float v[8];
    float mx = -1e30f;
    #pragma unroll
    for (int i = 0; i < 8; i++) { v[i] = simrow[t + i * 256]; mx = fmaxf(mx, v[i]); }
    mx = blockMax256(mx, buf);

    float s = 0.f;
    #pragma unroll
    for (int i = 0; i < 8; i++) { v[i] = __expf(beta * (v[i] - mx)); s += v[i]; }
    float Z = blockSum256(s, buf);

    const float* prev = (head < 2) ? (prev_ra + ((size_t)(head * B_ + b)) * A_)
                                   : (prev_wa + (size_t)b * A_);
    float gz = gate / Z, og = 1.f - gate;
    #pragma unroll
    for (int i = 0; i < 8; i++) {
        int a = t + i * 256;
        wg[a] = gz * v[i] + og * prev[a];
    }
    __syncthreads();

    float p[8];
    float ps = 0.f;
    #pragma unroll
    for (int i = 0; i < 8; i++) {
        int a = t + i * 256;
        float wsa = wg[(a + 1) & (A_ - 1)] * sw0 + wg[a] * sw1 + wg[(a - 1) & (A_ - 1)] * sw2;
        p[i] = __powf(wsa, gamma);
        ps += p[i];
    }
    float SP = blockSum256(ps, buf);
    float inv = 1.f / (SP + 1e-12f);
    float* wrow = g_w + ((size_t)(head * B_ + b)) * A_;
    #pragma unroll
    for (int i = 0; i < 8; i++) wrow[t + i * 256] = p[i] * inv;
}

// ---------------- k_update: float4 loads/stores (the ONE streaming change) --
// grid B*32, 256 threads (8 warps). Block = 64 a-rows; warp = 8 rows;
// lane = 4 channels (warp covers one full 512B row per step).
__global__ void k_update(const float* __restrict__ mem, float* __restrict__ out)
{
    __shared__ float wsm[3 * 64];
    __shared__ float rvs[2 * 8 * 128];     // [head][warp][c]
    int bx = blockIdx.x;
    int b  = bx >> 5;
    int a0 = (bx & 31) * 64;
    int t  = threadIdx.x;
    int w  = t >> 5, lane = t & 31;

    if (t < 192) {
        int head = t >> 6, aa = t & 63;
        wsm[t] = g_w[((size_t)(head * B_ + b)) * A_ + a0 + aa];
    }
    // erase / add for this lane's 4 channels
    float4 ev, av;
    {
        const float* pe = g_params + b * NP_ + NR_*PR_ +     C_ + 6 + lane * 4;
        const float* pa = g_params + b * NP_ + NR_*PR_ + 2 * C_ + 6 + lane * 4;
        ev.x = sigmoidf_(pe[0]); ev.y = sigmoidf_(pe[1]);
        ev.z = sigmoidf_(pe[2]); ev.w = sigmoidf_(pe[3]);
        av.x = sigmoidf_(pa[0]); av.y = sigmoidf_(pa[1]);
        av.z = sigmoidf_(pa[2]); av.w = sigmoidf_(pa[3]);
    }
    __syncthreads();

    const float4* mrow = (const float4*)mem + ((size_t)b * A_ + a0 + w * 8) * 32 + lane;
    float4* orow = (float4*)(out + (size_t)NR_ * B_ * C_)
                   + ((size_t)b * A_ + a0 + w * 8) * 32 + lane;

    float4 m[8];
    #pragma unroll
    for (int i = 0; i < 8; i++) m[i] = __ldcs(mrow + (size_t)i * 32);

    float4 rv0 = {0,0,0,0}, rv1 = {0,0,0,0};
    #pragma unroll
    for (int i = 0; i < 8; i++) {
        int aa = w * 8 + i;
        float w0 = wsm[aa], w1 = wsm[64 + aa], w2 = wsm[128 + aa];
        rv0.x = fmaf(w0, m[i].x, rv0.x); rv0.y = fmaf(w0, m[i].y, rv0.y);
        rv0.z = fmaf(w0, m[i].z, rv0.z); rv0.w = fmaf(w0, m[i].w, rv0.w);
        rv1.x = fmaf(w1, m[i].x, rv1.x); rv1.y = fmaf(w1, m[i].y, rv1.y);
        rv1.z = fmaf(w1, m[i].z, rv1.z); rv1.w = fmaf(w1, m[i].w, rv1.w);
        float4 o;
        o.x = fmaf(w2, av.x, m[i].x * (1.f - w2 * ev.x));
        o.y = fmaf(w2, av.y, m[i].y * (1.f - w2 * ev.y));
        o.z = fmaf(w2, av.z, m[i].z * (1.f - w2 * ev.z));
        o.w = fmaf(w2, av.w, m[i].w * (1.f - w2 * ev.w));
        __stcs(orow + (size_t)i * 32, o);
    }

    // cross-warp reduce of read-vector partials, then one atomic per (head,c)
    int c = lane * 4;
    rvs[(0 * 8 + w) * 128 + c]     = rv0.x;
    rvs[(0 * 8 + w) * 128 + c + 1] = rv0.y;
    rvs[(0 * 8 + w) * 128 + c + 2] = rv0.z;
    rvs[(0 * 8 + w) * 128 + c + 3] = rv0.w;
    rvs[(1 * 8 + w) * 128 + c]     = rv1.x;
    rvs[(1 * 8 + w) * 128 + c + 1] = rv1.y;
    rvs[(1 * 8 + w) * 128 + c + 2] = rv1.z;
    rvs[(1 * 8 + w) * 128 + c + 3] = rv1.w;
    __syncthreads();

    int head = t >> 7, cc = t & 127;
    float s = 0.f;
    #pragma unroll
    for (int ww = 0; ww < 8; ww++) s += rvs[(head * 8 + ww) * 128 + cc];
    atomicAdd(out + ((size_t)(head * B_ + b)) * C_ + cc, s);
}

// ---------------- launch -----------------------------------------------------
extern "C" void kernel_launch(void* const* d_in, const int* in_sizes, int n_in,
                              void* d_out, int out_size)
{
    const float* h   = (const float*)d_in[0];   // [B,H]
    const float* mem = (const float*)d_in[1];   // [B,A,C]
    const float* pra = (const float*)d_in[2];   // [NR,B,A]
    const float* pwa = (const float*)d_in[3];   // [B,A]
    const float* Wr  = (const float*)d_in[4];   // [NR,PR,H]
    const float* br  = (const float*)d_in[5];   // [NR,PR]
    const float* Ww  = (const float*)d_in[6];   // [PW,H]
    const float* bw  = (const float*)d_in[7];   // [PW]
    float* out = (float*)d_out;                 // [NR*B*C + B*A*C]

    dim3 gp((NP_ + 7) / 8, 4);
    k_proj<<<gp, 256>>>(h, Wr, br, Ww, bw);
    k_prep<<<B_, 128>>>(out);
    k_sim<<<B_ * 64, 256>>>(mem);
    dim3 ga(B_, 3);
    k_addr<<<ga, 256>>>(pra, pwa);
    k_update<<<B_ * 32, 256>>>(mem, out);
}